// round 1
// baseline (speedup 1.0000x reference)
#include <cuda_runtime.h>
#include <math.h>

#define BB 8
#define NN 192
#define HID 256
#define NF 32
#define RF 8
#define RS 16
#define IM 1024
#define LAYERS 3
#define HEADS 8
#define KS 32
#define KRS 16
#define VS 32
#define TOT 112
#define ROWS (BB*NN)          /* 1536 */
#define NPAIR (BB*NN*NN)      /* 294912 */

#define SCALE 0.14433756729740643f /* 1/sqrt(48) */
#define LN_EPS 1e-12f

// ---------------- scratch (device globals; no allocation allowed) ----------
__device__ float g_feat1[ROWS*HID];
__device__ float g_H[ROWS*HID];
__device__ float g_R[(size_t)NPAIR*RS];       // [b,i,j,s]
__device__ float g_H2[ROWS*HEADS*TOT];        // [b,n, h*112+t]
__device__ float g_A[ROWS*HEADS*KRS];         // [b,i, h*16+s]
__device__ float g_ctx[ROWS*HID];             // [b,i, h*32+v]
__device__ float g_attn[ROWS*HID];
__device__ float g_inter[ROWS*IM];
__device__ float g_tmp[ROWS*HID];

// ---------------- generic tiled SGEMM: C = A[M,K] @ B[K,N] (+bias, act) ----
// BM=BN=64, BK=16, 256 threads, 4x4 micro-tile. All dims divisible.
template<int ACT>
__global__ void gemm64(const float* __restrict__ A, const float* __restrict__ Bm,
                       const float* __restrict__ bias, float* __restrict__ C,
                       int M, int N, int K) {
    __shared__ float As[16][65];
    __shared__ float Bs[16][64];
    const int tid  = threadIdx.x;
    const int brow = blockIdx.y * 64;
    const int bcol = blockIdx.x * 64;
    const int tr = tid >> 4, tc = tid & 15;
    const int arow = tid >> 2, ac4 = tid & 3;
    const int brw = tid >> 4, bc4 = tid & 15;

    float acc[4][4] = {};
    for (int k0 = 0; k0 < K; k0 += 16) {
        float4 av = *(const float4*)(A + (size_t)(brow + arow) * K + k0 + ac4 * 4);
        As[ac4*4+0][arow] = av.x; As[ac4*4+1][arow] = av.y;
        As[ac4*4+2][arow] = av.z; As[ac4*4+3][arow] = av.w;
        *(float4*)(&Bs[brw][bc4*4]) =
            *(const float4*)(Bm + (size_t)(k0 + brw) * N + bcol + bc4 * 4);
        __syncthreads();
        #pragma unroll
        for (int k = 0; k < 16; k++) {
            float a[4];
            #pragma unroll
            for (int i = 0; i < 4; i++) a[i] = As[k][tr*4 + i];
            float4 bv = *(const float4*)(&Bs[k][tc*4]);
            float bb[4] = {bv.x, bv.y, bv.z, bv.w};
            #pragma unroll
            for (int i = 0; i < 4; i++)
                #pragma unroll
                for (int j = 0; j < 4; j++) acc[i][j] += a[i] * bb[j];
        }
        __syncthreads();
    }
    #pragma unroll
    for (int i = 0; i < 4; i++) {
        int r = brow + tr*4 + i;
        #pragma unroll
        for (int j = 0; j < 4; j++) {
            int c = bcol + tc*4 + j;
            float v = acc[i][j];
            if (bias) v += bias[c];
            if (ACT == 1) v = tanhf(v);
            if (ACT == 2) v = fmaxf(v, 0.0f);
            C[(size_t)r * N + c] = v;
        }
    }
}

// ---------------- block reduce (256 threads) -------------------------------
__device__ __forceinline__ float blocksum256(float v, float* red) {
    int tid = threadIdx.x;
    red[tid] = v; __syncthreads();
    if (tid < 128) red[tid] += red[tid + 128]; __syncthreads();
    if (tid < 64)  red[tid] += red[tid + 64];  __syncthreads();
    if (tid < 32) {
        float a = red[tid] + red[tid + 32];
        #pragma unroll
        for (int o = 16; o; o >>= 1) a += __shfl_xor_sync(0xffffffffu, a, o);
        if (tid == 0) red[0] = a;
    }
    __syncthreads();
    float r = red[0];
    __syncthreads();
    return r;
}

// ---------------- embeddings: H = LN(feat2 + emb[id]) ----------------------
__global__ void embed_ln_kernel(const float* __restrict__ pre, const int* __restrict__ ids,
                                const float* __restrict__ emb, const float* __restrict__ g,
                                const float* __restrict__ bt, float* __restrict__ out) {
    __shared__ float red[256];
    int row = blockIdx.x, tid = threadIdx.x;
    float v = pre[(size_t)row * HID + tid] + emb[(size_t)ids[row] * HID + tid];
    float mean = blocksum256(v, red) * (1.0f / HID);
    float d = v - mean;
    float var = blocksum256(d * d, red) * (1.0f / HID);
    out[(size_t)row * HID + tid] = g[tid] * d * rsqrtf(var + LN_EPS) + bt[tid];
}

// ---------------- out = LN(x + res) ----------------------------------------
__global__ void ln_res_kernel(const float* __restrict__ x, const float* __restrict__ res,
                              const float* __restrict__ g, const float* __restrict__ bt,
                              float* __restrict__ out) {
    __shared__ float red[256];
    int row = blockIdx.x, tid = threadIdx.x;
    float v = x[(size_t)row * HID + tid] + res[(size_t)row * HID + tid];
    float mean = blocksum256(v, red) * (1.0f / HID);
    float d = v - mean;
    float var = blocksum256(d * d, red) * (1.0f / HID);
    out[(size_t)row * HID + tid] = g[tid] * d * rsqrtf(var + LN_EPS) + bt[tid];
}

// ---------------- route embedding R = LN(tanh(rd@rw1+rb1)@rw2+rb2) ---------
__global__ void route_kernel(const float* __restrict__ rd,
                             const float* __restrict__ rw1, const float* __restrict__ rb1,
                             const float* __restrict__ rw2, const float* __restrict__ rb2,
                             const float* __restrict__ gg, const float* __restrict__ bb,
                             float* __restrict__ R) {
    __shared__ float s_rw1[RF*RS], s_rw2[RS*RS], s_rb1[RS], s_rb2[RS], s_g[RS], s_b[RS];
    int tid = threadIdx.x;
    for (int i = tid; i < RF*RS; i += blockDim.x) s_rw1[i] = rw1[i];
    for (int i = tid; i < RS*RS; i += blockDim.x) s_rw2[i] = rw2[i];
    if (tid < RS) { s_rb1[tid]=rb1[tid]; s_rb2[tid]=rb2[tid]; s_g[tid]=gg[tid]; s_b[tid]=bb[tid]; }
    __syncthreads();
    size_t idx = (size_t)blockIdx.x * blockDim.x + tid;   // exact multiple of NPAIR
    const float4* rp = (const float4*)(rd + idx * RF);
    float4 v0 = rp[0], v1 = rp[1];
    float x[RF] = {v0.x, v0.y, v0.z, v0.w, v1.x, v1.y, v1.z, v1.w};
    float h[RS];
    #pragma unroll
    for (int s = 0; s < RS; s++) {
        float a = s_rb1[s];
        #pragma unroll
        for (int f = 0; f < RF; f++) a += x[f] * s_rw1[f*RS + s];
        h[s] = tanhf(a);
    }
    float r[RS]; float mean = 0.0f;
    #pragma unroll
    for (int t = 0; t < RS; t++) {
        float a = s_rb2[t];
        #pragma unroll
        for (int s = 0; s < RS; s++) a += h[s] * s_rw2[s*RS + t];
        r[t] = a; mean += a;
    }
    mean *= (1.0f / RS);
    float var = 0.0f;
    #pragma unroll
    for (int t = 0; t < RS; t++) { float d = r[t] - mean; var += d * d; }
    var *= (1.0f / RS);
    float inv = rsqrtf(var + LN_EPS);
    float o[RS];
    #pragma unroll
    for (int t = 0; t < RS; t++) o[t] = s_g[t] * (r[t] - mean) * inv + s_b[t];
    float4* op = (float4*)(R + idx * RS);
    op[0] = make_float4(o[0],o[1],o[2],o[3]);
    op[1] = make_float4(o[4],o[5],o[6],o[7]);
    op[2] = make_float4(o[8],o[9],o[10],o[11]);
    op[3] = make_float4(o[12],o[13],o[14],o[15]);
}

// ---------------- A[b,i,h,s] = sum_k Qr[b,h,i,k] * Wd[s, h*16+k] -----------
__global__ void aqr_kernel(const float* __restrict__ H2, const float* __restrict__ Wd_l,
                           float* __restrict__ Aq) {
    __shared__ float sQr[HEADS*KRS];        // 128
    __shared__ float sWd[RS*HEADS*KRS];     // 2048
    int row = blockIdx.x, tid = threadIdx.x;   // 128 threads
    int h = tid >> 4, k = tid & 15;
    sQr[tid] = H2[(size_t)row * (HEADS*TOT) + h*TOT + 2*KS + VS + k];
    for (int i = tid; i < RS*HEADS*KRS; i += 128) sWd[i] = Wd_l[i];
    __syncthreads();
    int s = tid & 15;
    float a = 0.0f;
    #pragma unroll
    for (int kk = 0; kk < KRS; kk++)
        a += sQr[h*KRS + kk] * sWd[s*(HEADS*KRS) + h*KRS + kk];
    Aq[(size_t)row * (HEADS*KRS) + h*KRS + s] = a;
}

// ---------------- fused attention -----------------------------------------
// grid: (B*HEADS, 4), block 192. Per CTA: head (b,h), i in [i0, i0+48).
// smem: Kn,V for the whole (b,h), Wroute head slice; stream R[b,i] per row.
__global__ void attn_kernel(const float* __restrict__ H2, const float* __restrict__ R,
                            const float* __restrict__ Aq, const float* __restrict__ Wr_l,
                            const float* __restrict__ amask, float* __restrict__ ctx) {
    extern __shared__ float sm[];
    float* sKn   = sm;                    // 192*32
    float* sV    = sKn + NN*KS;           // 192*32
    float* sR    = sV + NN*VS;            // 192*16
    float* sWr   = sR + NN*RS;            // 16*32
    float* sMask = sWr + RS*VS;           // 192
    float* sP    = sMask + NN;            // 192
    float* red   = sP + NN;               // 192
    float* sQn   = red + NN;              // 32
    float* sA    = sQn + KS;              // 16
    float* sCtx  = sA + KRS;              // 32
    float* sPR   = sCtx + VS;             // 16

    const int tid = threadIdx.x;          // 0..191 (== j)
    const int b = blockIdx.x / HEADS, h = blockIdx.x % HEADS;

    const float* h2r = H2 + (size_t)(b*NN + tid) * (HEADS*TOT) + h*TOT;
    #pragma unroll
    for (int k = 0; k < KS/4; k++)
        ((float4*)(sKn + tid*KS))[k] = ((const float4*)(h2r + KS))[k];
    #pragma unroll
    for (int k = 0; k < VS/4; k++)
        ((float4*)(sV + tid*VS))[k]  = ((const float4*)(h2r + 2*KS))[k];
    sMask[tid] = (1.0f - amask[b*NN + tid]) * -10000.0f;
    for (int i2 = tid; i2 < RS*VS; i2 += blockDim.x) {
        int s = i2 / VS, v = i2 % VS;
        sWr[i2] = Wr_l[s*(HEADS*VS) + h*VS + v];
    }
    __syncthreads();

    const int i0 = blockIdx.y * (NN/4);
    for (int ii = 0; ii < NN/4; ii++) {
        int i = i0 + ii;
        // stream R[b,i,j,:] and per-i vectors
        const float4* rp = (const float4*)(R + ((size_t)(b*NN + i)*NN + tid) * RS);
        float4* sp = (float4*)(sR + tid*RS);
        sp[0]=rp[0]; sp[1]=rp[1]; sp[2]=rp[2]; sp[3]=rp[3];
        if (tid < KS)
            sQn[tid] = H2[(size_t)(b*NN + i)*(HEADS*TOT) + h*TOT + tid];
        else if (tid < KS + KRS)
            sA[tid - KS] = Aq[(size_t)(b*NN + i)*(HEADS*KRS) + h*KRS + (tid - KS)];
        else if (tid < KS + KRS + VS)
            sCtx[tid - KS - KRS] = 0.0f;
        else if (tid < KS + KRS + VS + RS)
            sPR[tid - KS - KRS - VS] = 0.0f;
        __syncthreads();

        // scores
        float sc = 0.0f;
        #pragma unroll
        for (int k = 0; k < KS; k++) sc += sQn[k] * sKn[tid*KS + k];
        #pragma unroll
        for (int s = 0; s < RS; s++) sc += sA[s] * sR[tid*RS + s];
        sc = sc * SCALE + sMask[tid];

        // softmax: max
        red[tid] = sc; __syncthreads();
        if (tid < 64) {
            float a = red[tid];
            a = fmaxf(a, red[tid + 64]); a = fmaxf(a, red[tid + 128]);
            red[tid] = a;
        }
        __syncthreads();
        if (tid < 32) {
            float a = fmaxf(red[tid], red[tid + 32]);
            #pragma unroll
            for (int o = 16; o; o >>= 1) a = fmaxf(a, __shfl_xor_sync(0xffffffffu, a, o));
            if (tid == 0) red[0] = a;
        }
        __syncthreads();
        float mx = red[0]; __syncthreads();
        float p = expf(sc - mx);
        red[tid] = p; __syncthreads();
        if (tid < 64) red[tid] += red[tid + 64] + red[tid + 128];
        __syncthreads();
        if (tid < 32) {
            float a = red[tid] + red[tid + 32];
            #pragma unroll
            for (int o = 16; o; o >>= 1) a += __shfl_xor_sync(0xffffffffu, a, o);
            if (tid == 0) red[0] = a;
        }
        __syncthreads();
        float inv = 1.0f / red[0]; __syncthreads();
        p *= inv;
        sP[tid] = p; __syncthreads();

        // ctx[v] = sum_j p_j * V[j,v]   (6 groups x 32 v)
        {
            int v = tid & 31, grp = tid >> 5;
            float part = 0.0f;
            const float* pv = sV + grp*32*VS + v;
            const float* pp = sP + grp*32;
            #pragma unroll
            for (int jj = 0; jj < 32; jj++) part += pp[jj] * pv[jj*VS];
            atomicAdd(&sCtx[v], part);
        }
        // PR[s] = sum_j p_j * R[j,s]    (12 groups x 16 s)
        {
            int s = tid & 15, grp = tid >> 4;
            float part = 0.0f;
            const float* pr = sR + grp*16*RS + s;
            const float* pp = sP + grp*16;
            #pragma unroll
            for (int jj = 0; jj < 16; jj++) part += pp[jj] * pr[jj*RS];
            atomicAdd(&sPR[s], part);
        }
        __syncthreads();

        if (tid < VS) {
            float c = sCtx[tid];
            #pragma unroll
            for (int s = 0; s < RS; s++) c += sPR[s] * sWr[s*VS + tid];
            ctx[(size_t)(b*NN + i) * HID + h*VS + tid] = c;
        }
        __syncthreads();
    }
}

// ---------------- host launch ----------------------------------------------
extern "C" void kernel_launch(void* const* d_in, const int* in_sizes, int n_in,
                              void* d_out, int out_size) {
    const int*   node_ids      = (const int*)  d_in[0];
    const float* node_features = (const float*)d_in[1];
    const float* route_data    = (const float*)d_in[2];
    const float* amask         = (const float*)d_in[3];
    const float* emb           = (const float*)d_in[4];
    const float* fw1 = (const float*)d_in[5];  const float* fb1 = (const float*)d_in[6];
    const float* fw2 = (const float*)d_in[7];  const float* fb2 = (const float*)d_in[8];
    const float* eg  = (const float*)d_in[9];  const float* ebt = (const float*)d_in[10];
    const float* rw1 = (const float*)d_in[11]; const float* rb1 = (const float*)d_in[12];
    const float* rw2 = (const float*)d_in[13]; const float* rb2 = (const float*)d_in[14];
    const float* rg  = (const float*)d_in[15]; const float* rbt = (const float*)d_in[16];
    const float* W      = (const float*)d_in[17];
    const float* Wd     = (const float*)d_in[18];
    const float* Wroute = (const float*)d_in[19];
    const float* Wo     = (const float*)d_in[20];
    const float* bo     = (const float*)d_in[21];
    const float* og     = (const float*)d_in[22]; const float* obt = (const float*)d_in[23];
    const float* Wi     = (const float*)d_in[24]; const float* bi  = (const float*)d_in[25];
    const float* Wo2    = (const float*)d_in[26]; const float* bo2 = (const float*)d_in[27];
    const float* fg     = (const float*)d_in[28]; const float* fbt = (const float*)d_in[29];
    float* out = (float*)d_out;

    float *pH, *pFeat1, *pR, *pH2, *pA, *pCtx, *pAttn, *pInter, *pTmp;
    cudaGetSymbolAddress((void**)&pH,     g_H);
    cudaGetSymbolAddress((void**)&pFeat1, g_feat1);
    cudaGetSymbolAddress((void**)&pR,     g_R);
    cudaGetSymbolAddress((void**)&pH2,    g_H2);
    cudaGetSymbolAddress((void**)&pA,     g_A);
    cudaGetSymbolAddress((void**)&pCtx,   g_ctx);
    cudaGetSymbolAddress((void**)&pAttn,  g_attn);
    cudaGetSymbolAddress((void**)&pInter, g_inter);
    cudaGetSymbolAddress((void**)&pTmp,   g_tmp);

    const int ATTN_SMEM = (NN*KS + NN*VS + NN*RS + RS*VS + NN + NN + NN
                           + KS + KRS + VS + RS) * (int)sizeof(float);
    cudaFuncSetAttribute(attn_kernel, cudaFuncAttributeMaxDynamicSharedMemorySize, ATTN_SMEM);

    dim3 blk256(256);

    // --- embeddings ---
    gemm64<1><<<dim3(HID/64, ROWS/64), blk256>>>(node_features, fw1, fb1, pFeat1,
                                                 ROWS, HID, NF);
    gemm64<0><<<dim3(HID/64, ROWS/64), blk256>>>(pFeat1, fw2, fb2, pTmp,
                                                 ROWS, HID, HID);
    embed_ln_kernel<<<ROWS, 256>>>(pTmp, node_ids, emb, eg, ebt, pH);

    // --- route embeddings ---
    route_kernel<<<NPAIR/256, 256>>>(route_data, rw1, rb1, rw2, rb2, rg, rbt, pR);

    // --- layers ---
    for (int l = 0; l < LAYERS; l++) {
        const float* W_l   = W      + (size_t)l * HID * (HEADS*TOT);
        const float* Wd_l  = Wd     + (size_t)l * RS * (HEADS*KRS);
        const float* Wr_l  = Wroute + (size_t)l * RS * (HEADS*VS);
        const float* Wo_l  = Wo     + (size_t)l * HID * HID;
        const float* bo_l  = bo     + (size_t)l * HID;
        const float* og_l  = og     + (size_t)l * HID;
        const float* ob_l  = obt    + (size_t)l * HID;
        const float* Wi_l  = Wi     + (size_t)l * HID * IM;
        const float* bi_l  = bi     + (size_t)l * IM;
        const float* W2_l  = Wo2    + (size_t)l * IM * HID;
        const float* b2_l  = bo2    + (size_t)l * HID;
        const float* fg_l  = fg     + (size_t)l * HID;
        const float* fb_l  = fbt    + (size_t)l * HID;

        // QKV projection: H2 = H @ W_l   [1536 x 896]
        gemm64<0><<<dim3((HEADS*TOT)/64, ROWS/64), blk256>>>(pH, W_l, nullptr, pH2,
                                                             ROWS, HEADS*TOT, HID);
        // route-key factor A
        aqr_kernel<<<ROWS, 128>>>(pH2, Wd_l, pA);
        // fused attention -> ctx [1536 x 256]
        attn_kernel<<<dim3(BB*HEADS, 4), dim3(NN), ATTN_SMEM>>>(pH2, pR, pA, Wr_l,
                                                                amask, pCtx);
        // output projection + residual LN
        gemm64<0><<<dim3(HID/64, ROWS/64), blk256>>>(pCtx, Wo_l, bo_l, pTmp,
                                                     ROWS, HID, HID);
        ln_res_kernel<<<ROWS, 256>>>(pTmp, pH, og_l, ob_l, pAttn);
        // FFN
        gemm64<2><<<dim3(IM/64, ROWS/64), blk256>>>(pAttn, Wi_l, bi_l, pInter,
                                                    ROWS, IM, HID);
        gemm64<0><<<dim3(HID/64, ROWS/64), blk256>>>(pInter, W2_l, b2_l, pTmp,
                                                     ROWS, HID, IM);
        float* dst = (l == LAYERS - 1) ? out : pH;
        ln_res_kernel<<<ROWS, 256>>>(pTmp, pAttn, fg_l, fb_l, dst);
    }
    (void)in_sizes; (void)n_in; (void)out_size;
}

// round 2
// speedup vs baseline: 1.7121x; 1.7121x over previous
#include <cuda_runtime.h>
#include <math.h>
#include <stdint.h>

#define BB 8
#define NN 192
#define HID 256
#define NF 32
#define RF 8
#define RS 16
#define IM 1024
#define LAYERS 3
#define HEADS 8
#define KS 32
#define KRS 16
#define VS 32
#define TOT 112
#define ROWS (BB*NN)          /* 1536 */
#define NPAIR (BB*NN*NN)      /* 294912 */

#define SCALE 0.14433756729740643f /* 1/sqrt(48) */
#define LN_EPS 1e-12f

// ---------------- scratch (device globals; no allocation allowed) ----------
__device__ float g_feat1[ROWS*HID];
__device__ float g_H[ROWS*HID];
__device__ float g_R[(size_t)NPAIR*RS];       // [b,i,j,s]
__device__ float g_H2[ROWS*HEADS*TOT];        // [b,n, h*112+t]
__device__ float g_A[ROWS*HEADS*KRS];         // [b,i, h*16+s]
__device__ float g_ctx[ROWS*HID];             // [b,i, h*32+v]
__device__ float g_attn[ROWS*HID];
__device__ float g_inter[ROWS*IM];
__device__ float g_tmp[ROWS*HID];

// ---------------- tf32 tensor-core GEMM ------------------------------------
// C[M,N] = A[M,K] @ B[K,N] (+bias, activation). BM=128, BN=64, BK=16,
// 256 threads = 8 warps (4 in M x 2 in N), warp tile 32x32 via m16n8k8 tf32.
__device__ __forceinline__ uint32_t f2tf32(float f) {
    uint32_t r;
    asm("cvt.rna.tf32.f32 %0, %1;" : "=r"(r) : "f"(f));
    return r;
}
__device__ __forceinline__ void mma_tf32(float* c,
        uint32_t a0, uint32_t a1, uint32_t a2, uint32_t a3,
        uint32_t b0, uint32_t b1) {
    asm("mma.sync.aligned.m16n8k8.row.col.f32.tf32.tf32.f32 "
        "{%0,%1,%2,%3},{%4,%5,%6,%7},{%8,%9},{%0,%1,%2,%3};"
        : "+f"(c[0]), "+f"(c[1]), "+f"(c[2]), "+f"(c[3])
        : "r"(a0), "r"(a1), "r"(a2), "r"(a3), "r"(b0), "r"(b1));
}

template<int ACT>
__global__ void gemm_tc(const float* __restrict__ A, const float* __restrict__ Bm,
                        const float* __restrict__ bias, float* __restrict__ C,
                        int M, int N, int K) {
    __shared__ float As[128][20];   // stride 20 -> conflict-free frag loads
    __shared__ float Bs[16][72];    // stride 72 -> conflict-free frag loads
    const int tid = threadIdx.x, lane = tid & 31, wid = tid >> 5;
    const int wm = (wid >> 1) * 32, wn = (wid & 1) * 32;
    const int brow = blockIdx.y * 128, bcol = blockIdx.x * 64;
    const int g = lane >> 2, t4 = lane & 3;
    const int ar = tid >> 1, ac = (tid & 1) * 8;
    const int br_ = tid >> 4, bc_ = (tid & 15) * 4;

    float acc[2][4][4] = {};
    for (int k0 = 0; k0 < K; k0 += 16) {
        float4 v0 = *(const float4*)(A + (size_t)(brow + ar) * K + k0 + ac);
        float4 v1 = *(const float4*)(A + (size_t)(brow + ar) * K + k0 + ac + 4);
        As[ar][ac+0] = v0.x; As[ar][ac+1] = v0.y; As[ar][ac+2] = v0.z; As[ar][ac+3] = v0.w;
        As[ar][ac+4] = v1.x; As[ar][ac+5] = v1.y; As[ar][ac+6] = v1.z; As[ar][ac+7] = v1.w;
        *(float4*)(&Bs[br_][bc_]) = *(const float4*)(Bm + (size_t)(k0 + br_) * N + bcol + bc_);
        __syncthreads();
        #pragma unroll
        for (int kf = 0; kf < 16; kf += 8) {
            uint32_t a[2][4], b[4][2];
            #pragma unroll
            for (int mi = 0; mi < 2; mi++) {
                int r0 = wm + mi * 16 + g;
                a[mi][0] = f2tf32(As[r0][kf + t4]);
                a[mi][1] = f2tf32(As[r0 + 8][kf + t4]);
                a[mi][2] = f2tf32(As[r0][kf + t4 + 4]);
                a[mi][3] = f2tf32(As[r0 + 8][kf + t4 + 4]);
            }
            #pragma unroll
            for (int ni = 0; ni < 4; ni++) {
                int c0 = wn + ni * 8 + g;
                b[ni][0] = f2tf32(Bs[kf + t4][c0]);
                b[ni][1] = f2tf32(Bs[kf + t4 + 4][c0]);
            }
            #pragma unroll
            for (int mi = 0; mi < 2; mi++)
                #pragma unroll
                for (int ni = 0; ni < 4; ni++)
                    mma_tf32(acc[mi][ni], a[mi][0], a[mi][1], a[mi][2], a[mi][3],
                             b[ni][0], b[ni][1]);
        }
        __syncthreads();
    }
    #pragma unroll
    for (int mi = 0; mi < 2; mi++) {
        #pragma unroll
        for (int ni = 0; ni < 4; ni++) {
            int r = brow + wm + mi * 16 + g;
            int c = bcol + wn + ni * 8 + t4 * 2;
            #pragma unroll
            for (int e = 0; e < 4; e++) {
                int rr = r + ((e >= 2) ? 8 : 0);
                int cc = c + (e & 1);
                float v = acc[mi][ni][e];
                if (bias) v += bias[cc];
                if (ACT == 1) v = tanhf(v);
                if (ACT == 2) v = fmaxf(v, 0.0f);
                C[(size_t)rr * N + cc] = v;
            }
        }
    }
}

// ---------------- block reduce (256 threads) -------------------------------
__device__ __forceinline__ float blocksum256(float v, float* red) {
    int tid = threadIdx.x;
    red[tid] = v; __syncthreads();
    if (tid < 128) red[tid] += red[tid + 128]; __syncthreads();
    if (tid < 64)  red[tid] += red[tid + 64];  __syncthreads();
    if (tid < 32) {
        float a = red[tid] + red[tid + 32];
        #pragma unroll
        for (int o = 16; o; o >>= 1) a += __shfl_xor_sync(0xffffffffu, a, o);
        if (tid == 0) red[0] = a;
    }
    __syncthreads();
    float r = red[0];
    __syncthreads();
    return r;
}

// ---------------- embeddings: H = LN(feat2 + emb[id]) ----------------------
__global__ void embed_ln_kernel(const float* __restrict__ pre, const int* __restrict__ ids,
                                const float* __restrict__ emb, const float* __restrict__ g,
                                const float* __restrict__ bt, float* __restrict__ out) {
    __shared__ float red[256];
    int row = blockIdx.x, tid = threadIdx.x;
    float v = pre[(size_t)row * HID + tid] + emb[(size_t)ids[row] * HID + tid];
    float mean = blocksum256(v, red) * (1.0f / HID);
    float d = v - mean;
    float var = blocksum256(d * d, red) * (1.0f / HID);
    out[(size_t)row * HID + tid] = g[tid] * d * rsqrtf(var + LN_EPS) + bt[tid];
}

// ---------------- out = LN(x + res) ----------------------------------------
__global__ void ln_res_kernel(const float* __restrict__ x, const float* __restrict__ res,
                              const float* __restrict__ g, const float* __restrict__ bt,
                              float* __restrict__ out) {
    __shared__ float red[256];
    int row = blockIdx.x, tid = threadIdx.x;
    float v = x[(size_t)row * HID + tid] + res[(size_t)row * HID + tid];
    float mean = blocksum256(v, red) * (1.0f / HID);
    float d = v - mean;
    float var = blocksum256(d * d, red) * (1.0f / HID);
    out[(size_t)row * HID + tid] = g[tid] * d * rsqrtf(var + LN_EPS) + bt[tid];
}

// ---------------- route embedding R = LN(tanh(rd@rw1+rb1)@rw2+rb2) ---------
__global__ void route_kernel(const float* __restrict__ rd,
                             const float* __restrict__ rw1, const float* __restrict__ rb1,
                             const float* __restrict__ rw2, const float* __restrict__ rb2,
                             const float* __restrict__ gg, const float* __restrict__ bb,
                             float* __restrict__ R) {
    __shared__ float s_rw1[RF*RS], s_rw2[RS*RS], s_rb1[RS], s_rb2[RS], s_g[RS], s_b[RS];
    int tid = threadIdx.x;
    for (int i = tid; i < RF*RS; i += blockDim.x) s_rw1[i] = rw1[i];
    for (int i = tid; i < RS*RS; i += blockDim.x) s_rw2[i] = rw2[i];
    if (tid < RS) { s_rb1[tid]=rb1[tid]; s_rb2[tid]=rb2[tid]; s_g[tid]=gg[tid]; s_b[tid]=bb[tid]; }
    __syncthreads();
    size_t idx = (size_t)blockIdx.x * blockDim.x + tid;
    const float4* rp = (const float4*)(rd + idx * RF);
    float4 v0 = rp[0], v1 = rp[1];
    float x[RF] = {v0.x, v0.y, v0.z, v0.w, v1.x, v1.y, v1.z, v1.w};
    float h[RS];
    #pragma unroll
    for (int s = 0; s < RS; s++) {
        float a = s_rb1[s];
        #pragma unroll
        for (int f = 0; f < RF; f++) a += x[f] * s_rw1[f*RS + s];
        h[s] = tanhf(a);
    }
    float r[RS]; float mean = 0.0f;
    #pragma unroll
    for (int t = 0; t < RS; t++) {
        float a = s_rb2[t];
        #pragma unroll
        for (int s = 0; s < RS; s++) a += h[s] * s_rw2[s*RS + t];
        r[t] = a; mean += a;
    }
    mean *= (1.0f / RS);
    float var = 0.0f;
    #pragma unroll
    for (int t = 0; t < RS; t++) { float d = r[t] - mean; var += d * d; }
    var *= (1.0f / RS);
    float inv = rsqrtf(var + LN_EPS);
    float o[RS];
    #pragma unroll
    for (int t = 0; t < RS; t++) o[t] = s_g[t] * (r[t] - mean) * inv + s_b[t];
    float4* op = (float4*)(R + idx * RS);
    op[0] = make_float4(o[0],o[1],o[2],o[3]);
    op[1] = make_float4(o[4],o[5],o[6],o[7]);
    op[2] = make_float4(o[8],o[9],o[10],o[11]);
    op[3] = make_float4(o[12],o[13],o[14],o[15]);
}

// ---------------- A[b,i,h,s] = sum_k Qr[b,h,i,k] * Wd[s, h*16+k] -----------
__global__ void aqr_kernel(const float* __restrict__ H2, const float* __restrict__ Wd_l,
                           float* __restrict__ Aq) {
    __shared__ float sQr[HEADS*KRS];        // 128
    __shared__ float sWd[RS*HEADS*KRS];     // 2048
    int row = blockIdx.x, tid = threadIdx.x;   // 128 threads
    int h = tid >> 4, k = tid & 15;
    sQr[tid] = H2[(size_t)row * (HEADS*TOT) + h*TOT + 2*KS + VS + k];
    for (int i = tid; i < RS*HEADS*KRS; i += 128) sWd[i] = Wd_l[i];
    __syncthreads();
    int s = tid & 15;
    float a = 0.0f;
    #pragma unroll
    for (int kk = 0; kk < KRS; kk++)
        a += sQr[h*KRS + kk] * sWd[s*(HEADS*KRS) + h*KRS + kk];
    Aq[(size_t)row * (HEADS*KRS) + h*KRS + s] = a;
}

// ---------------- fused attention -------------------------------------------
// grid: (B*HEADS, 4), block 192. Per CTA: head (b,h), i in [i0, i0+48).
// Padded smem strides (33 / 17) -> all hot LDS conflict-free. 4 barriers/row.
#define KSTR 33
#define RSTR 17
__global__ void attn_kernel(const float* __restrict__ H2, const float* __restrict__ R,
                            const float* __restrict__ Aq, const float* __restrict__ Wr_l,
                            const float* __restrict__ amask, float* __restrict__ ctx) {
    extern __shared__ float sm[];
    float* sKn    = sm;                     // 192*33
    float* sV     = sKn + NN*KSTR;          // 192*33
    float* sR     = sV + NN*KSTR;           // 192*17
    float* sWr    = sR + NN*RSTR;           // 16*32
    float* sMask  = sWr + RS*VS;            // 192
    float* sP     = sMask + NN;             // 192
    float* red    = sP + NN;                // 8
    float* sQn    = red + 8;                // 32
    float* sA     = sQn + KS;               // 16
    float* sCtxP  = sA + KRS;               // 6*32
    float* sPRP   = sCtxP + 6*32;           // 12*16
    float* sPR    = sPRP + 12*16;           // 16

    const int tid = threadIdx.x;            // 0..191 (== j)
    const int lane = tid & 31, wid = tid >> 5;
    const int b = blockIdx.x / HEADS, h = blockIdx.x % HEADS;

    const float* h2r = H2 + (size_t)(b*NN + tid) * (HEADS*TOT) + h*TOT;
    #pragma unroll
    for (int k4 = 0; k4 < KS/4; k4++) {
        float4 kv = ((const float4*)(h2r + KS))[k4];
        sKn[tid*KSTR + k4*4+0] = kv.x; sKn[tid*KSTR + k4*4+1] = kv.y;
        sKn[tid*KSTR + k4*4+2] = kv.z; sKn[tid*KSTR + k4*4+3] = kv.w;
        float4 vv = ((const float4*)(h2r + 2*KS))[k4];
        sV[tid*KSTR + k4*4+0] = vv.x; sV[tid*KSTR + k4*4+1] = vv.y;
        sV[tid*KSTR + k4*4+2] = vv.z; sV[tid*KSTR + k4*4+3] = vv.w;
    }
    sMask[tid] = (1.0f - amask[b*NN + tid]) * -10000.0f;
    for (int i2 = tid; i2 < RS*VS; i2 += blockDim.x) {
        int s = i2 / VS, v = i2 % VS;
        sWr[i2] = Wr_l[s*(HEADS*VS) + h*VS + v];
    }
    __syncthreads();

    const int i0 = blockIdx.y * (NN/4);
    for (int ii = 0; ii < NN/4; ii++) {
        int i = i0 + ii;
        // load R[b,i,tid,:] into padded smem
        {
            const float4* rp = (const float4*)(R + ((size_t)(b*NN + i)*NN + tid) * RS);
            #pragma unroll
            for (int q = 0; q < 4; q++) {
                float4 rv = rp[q];
                sR[tid*RSTR + q*4+0] = rv.x; sR[tid*RSTR + q*4+1] = rv.y;
                sR[tid*RSTR + q*4+2] = rv.z; sR[tid*RSTR + q*4+3] = rv.w;
            }
        }
        if (tid < KS)
            sQn[tid] = H2[(size_t)(b*NN + i)*(HEADS*TOT) + h*TOT + tid];
        else if (tid < KS + KRS)
            sA[tid - KS] = Aq[(size_t)(b*NN + i)*(HEADS*KRS) + h*KRS + (tid - KS)];
        __syncthreads();                                   // B1

        // scores + exp (no max-subtract: additive mask, |score| bounded)
        float sc = 0.0f;
        #pragma unroll
        for (int k = 0; k < KS; k++) sc += sQn[k] * sKn[tid*KSTR + k];
        #pragma unroll
        for (int s = 0; s < RS; s++) sc += sA[s] * sR[tid*RSTR + s];
        float p = __expf(sc * SCALE + sMask[tid]);
        float a = p;
        #pragma unroll
        for (int o = 16; o; o >>= 1) a += __shfl_xor_sync(0xffffffffu, a, o);
        if (lane == 0) red[wid] = a;
        sP[tid] = p;
        __syncthreads();                                   // B2

        float inv = 1.0f / (red[0] + red[1] + red[2] + red[3] + red[4] + red[5]);

        // ctx partials: thread (grp = tid>>5, v = tid&31)
        {
            int v = lane, grp = wid;
            float part = 0.0f;
            const float* pp = sP + grp*32;
            const float* pv = sV + (size_t)grp*32*KSTR + v;
            #pragma unroll
            for (int jj = 0; jj < 32; jj++) part += pp[jj] * pv[jj*KSTR];
            sCtxP[grp*32 + v] = part * inv;
        }
        // PR partials: thread (g2 = tid>>4, s = tid&15)
        {
            int s = tid & 15, g2 = tid >> 4;
            float part = 0.0f;
            const float* pp = sP + g2*16;
            const float* pr = sR + (size_t)g2*16*RSTR + s;
            #pragma unroll
            for (int jj = 0; jj < 16; jj++) part += pp[jj] * pr[jj*RSTR];
            sPRP[g2*16 + s] = part * inv;
        }
        __syncthreads();                                   // B3

        float csum = 0.0f;
        if (tid < VS) {
            #pragma unroll
            for (int g = 0; g < 6; g++) csum += sCtxP[g*32 + tid];
        } else if (tid < VS + RS) {
            int s = tid - VS;
            float a2 = 0.0f;
            #pragma unroll
            for (int g = 0; g < 12; g++) a2 += sPRP[g*16 + s];
            sPR[s] = a2;
        }
        __syncthreads();                                   // B4

        if (tid < VS) {
            float c = csum;
            #pragma unroll
            for (int s = 0; s < RS; s++) c += sPR[s] * sWr[s*VS + tid];
            ctx[(size_t)(b*NN + i) * HID + h*VS + tid] = c;
        }
    }
}

// ---------------- host launch ------------------------------------------------
extern "C" void kernel_launch(void* const* d_in, const int* in_sizes, int n_in,
                              void* d_out, int out_size) {
    const int*   node_ids      = (const int*)  d_in[0];
    const float* node_features = (const float*)d_in[1];
    const float* route_data    = (const float*)d_in[2];
    const float* amask         = (const float*)d_in[3];
    const float* emb           = (const float*)d_in[4];
    const float* fw1 = (const float*)d_in[5];  const float* fb1 = (const float*)d_in[6];
    const float* fw2 = (const float*)d_in[7];  const float* fb2 = (const float*)d_in[8];
    const float* eg  = (const float*)d_in[9];  const float* ebt = (const float*)d_in[10];
    const float* rw1 = (const float*)d_in[11]; const float* rb1 = (const float*)d_in[12];
    const float* rw2 = (const float*)d_in[13]; const float* rb2 = (const float*)d_in[14];
    const float* rg  = (const float*)d_in[15]; const float* rbt = (const float*)d_in[16];
    const float* W      = (const float*)d_in[17];
    const float* Wd     = (const float*)d_in[18];
    const float* Wroute = (const float*)d_in[19];
    const float* Wo     = (const float*)d_in[20];
    const float* bo     = (const float*)d_in[21];
    const float* og     = (const float*)d_in[22]; const float* obt = (const float*)d_in[23];
    const float* Wi     = (const float*)d_in[24]; const float* bi  = (const float*)d_in[25];
    const float* Wo2    = (const float*)d_in[26]; const float* bo2 = (const float*)d_in[27];
    const float* fg     = (const float*)d_in[28]; const float* fbt = (const float*)d_in[29];
    float* out = (float*)d_out;

    float *pH, *pFeat1, *pR, *pH2, *pA, *pCtx, *pAttn, *pInter, *pTmp;
    cudaGetSymbolAddress((void**)&pH,     g_H);
    cudaGetSymbolAddress((void**)&pFeat1, g_feat1);
    cudaGetSymbolAddress((void**)&pR,     g_R);
    cudaGetSymbolAddress((void**)&pH2,    g_H2);
    cudaGetSymbolAddress((void**)&pA,     g_A);
    cudaGetSymbolAddress((void**)&pCtx,   g_ctx);
    cudaGetSymbolAddress((void**)&pAttn,  g_attn);
    cudaGetSymbolAddress((void**)&pInter, g_inter);
    cudaGetSymbolAddress((void**)&pTmp,   g_tmp);

    const int ATTN_SMEM = (NN*KSTR*2 + NN*RSTR + RS*VS + NN + NN + 8
                           + KS + KRS + 6*32 + 12*16 + RS) * (int)sizeof(float);
    cudaFuncSetAttribute(attn_kernel, cudaFuncAttributeMaxDynamicSharedMemorySize, ATTN_SMEM);

    dim3 blk256(256);

    // --- embeddings ---
    gemm_tc<1><<<dim3(HID/64, ROWS/128), blk256>>>(node_features, fw1, fb1, pFeat1,
                                                   ROWS, HID, NF);
    gemm_tc<0><<<dim3(HID/64, ROWS/128), blk256>>>(pFeat1, fw2, fb2, pTmp,
                                                   ROWS, HID, HID);
    embed_ln_kernel<<<ROWS, 256>>>(pTmp, node_ids, emb, eg, ebt, pH);

    // --- route embeddings ---
    route_kernel<<<NPAIR/256, 256>>>(route_data, rw1, rb1, rw2, rb2, rg, rbt, pR);

    // --- layers ---
    for (int l = 0; l < LAYERS; l++) {
        const float* W_l   = W      + (size_t)l * HID * (HEADS*TOT);
        const float* Wd_l  = Wd     + (size_t)l * RS * (HEADS*KRS);
        const float* Wr_l  = Wroute + (size_t)l * RS * (HEADS*VS);
        const float* Wo_l  = Wo     + (size_t)l * HID * HID;
        const float* bo_l  = bo     + (size_t)l * HID;
        const float* og_l  = og     + (size_t)l * HID;
        const float* ob_l  = obt    + (size_t)l * HID;
        const float* Wi_l  = Wi     + (size_t)l * HID * IM;
        const float* bi_l  = bi     + (size_t)l * IM;
        const float* W2_l  = Wo2    + (size_t)l * IM * HID;
        const float* b2_l  = bo2    + (size_t)l * HID;
        const float* fg_l  = fg     + (size_t)l * HID;
        const float* fb_l  = fbt    + (size_t)l * HID;

        // QKV projection: H2 = H @ W_l   [1536 x 896]
        gemm_tc<0><<<dim3((HEADS*TOT)/64, ROWS/128), blk256>>>(pH, W_l, nullptr, pH2,
                                                               ROWS, HEADS*TOT, HID);
        // route-key factor A
        aqr_kernel<<<ROWS, 128>>>(pH2, Wd_l, pA);
        // fused attention -> ctx [1536 x 256]
        attn_kernel<<<dim3(BB*HEADS, 4), dim3(NN), ATTN_SMEM>>>(pH2, pR, pA, Wr_l,
                                                                amask, pCtx);
        // output projection + residual LN
        gemm_tc<0><<<dim3(HID/64, ROWS/128), blk256>>>(pCtx, Wo_l, bo_l, pTmp,
                                                       ROWS, HID, HID);
        ln_res_kernel<<<ROWS, 256>>>(pTmp, pH, og_l, ob_l, pAttn);
        // FFN
        gemm_tc<2><<<dim3(IM/64, ROWS/128), blk256>>>(pAttn, Wi_l, bi_l, pInter,
                                                      ROWS, IM, HID);
        gemm_tc<0><<<dim3(HID/64, ROWS/128), blk256>>>(pInter, W2_l, b2_l, pTmp,
                                                       ROWS, HID, IM);
        float* dst = (l == LAYERS - 1) ? out : pH;
        ln_res_kernel<<<ROWS, 256>>>(pTmp, pAttn, fg_l, fb_l, dst);
    }
    (void)in_sizes; (void)n_in; (void)out_size;
}